// round 8
// baseline (speedup 1.0000x reference)
#include <cuda_runtime.h>
#include <cuda_bf16.h>
#include <math.h>
#include <stdint.h>

#define Gg 8
#define Ee 8
#define Ss 1024
#define Cc 256
#define Mdim 1024
#define Hh 5464
#define Hp 5504
#define Ntok (Gg*Ss)
#define GCv (Gg*Cc)

// ---------------- device scratch ----------------
__device__ __align__(256) __nv_bfloat16 g_a_hi [(size_t)Ee*GCv*Mdim];
__device__ __align__(256) __nv_bfloat16 g_a_lo [(size_t)Ee*GCv*Mdim];
__device__ __align__(256) __nv_bfloat16 g_w0t_hi[(size_t)Ee*Hp*Mdim];
__device__ __align__(256) __nv_bfloat16 g_w0t_lo[(size_t)Ee*Hp*Mdim];
__device__ __align__(256) __nv_bfloat16 g_w1t_hi[(size_t)Ee*Hp*Mdim];
__device__ __align__(256) __nv_bfloat16 g_w1t_lo[(size_t)Ee*Hp*Mdim];
__device__ __align__(256) __nv_bfloat16 g_wot_hi[(size_t)Ee*Mdim*Hp];
__device__ __align__(256) __nv_bfloat16 g_wot_lo[(size_t)Ee*Mdim*Hp];
__device__ __align__(256) __nv_bfloat16 g_hid_hi[(size_t)Ee*GCv*Hp];
__device__ __align__(256) __nv_bfloat16 g_hid_lo[(size_t)Ee*GCv*Hp];
__device__ __align__(256) float g_acc0  [(size_t)Ee*GCv*Hp];
__device__ __align__(256) float g_expout[(size_t)Ee*GCv*Mdim];
__device__ int   g_idx1[Ntok];
__device__ int   g_idx2[Ntok];
__device__ float g_gate1[Ntok];
__device__ float g_gate2[Ntok];
__device__ int   g_slotsrc[Ee*GCv];
__device__ int2  g_tokinfo[Ntok];

// ---------------- helpers ----------------
__device__ __forceinline__ uint32_t s2u(const void* p){
    uint32_t a; asm("{ .reg .u64 t; cvta.to.shared.u64 t, %1; cvt.u32.u64 %0, t; }":"=r"(a):"l"(p)); return a;
}
__device__ __forceinline__ void cpa16(uint32_t d, const void* s){
    asm volatile("cp.async.cg.shared.global [%0], [%1], 16;"::"r"(d),"l"(s));
}
#define CP_COMMIT() asm volatile("cp.async.commit_group;":::"memory")
#define CP_WAIT2()  asm volatile("cp.async.wait_group 2;":::"memory")
#define CP_WAIT1()  asm volatile("cp.async.wait_group 1;":::"memory")
#define CP_WAIT0()  asm volatile("cp.async.wait_group 0;":::"memory")

#define LDSM4(R, addr) \
    asm volatile("ldmatrix.sync.aligned.m8n8.x4.shared.b16 {%0,%1,%2,%3}, [%4];" \
        : "=r"((R)[0]),"=r"((R)[1]),"=r"((R)[2]),"=r"((R)[3]) : "r"(addr))
#define LDSM2(R, addr) \
    asm volatile("ldmatrix.sync.aligned.m8n8.x2.shared.b16 {%0,%1}, [%2];" \
        : "=r"((R)[0]),"=r"((R)[1]) : "r"(addr))
#define MMA_BF16(D, A, B) \
    asm volatile("mma.sync.aligned.m16n8k16.row.col.f32.bf16.bf16.f32 " \
        "{%0,%1,%2,%3}, {%4,%5,%6,%7}, {%8,%9}, {%0,%1,%2,%3};" \
        : "+f"((D)[0]),"+f"((D)[1]),"+f"((D)[2]),"+f"((D)[3]) \
        : "r"((A)[0]),"r"((A)[1]),"r"((A)[2]),"r"((A)[3]), "r"((B)[0]),"r"((B)[1]))

__device__ __forceinline__ void split1(float a, __nv_bfloat16& h, __nv_bfloat16& l){
    h = __float2bfloat16(a); l = __float2bfloat16(a - __bfloat162float(h));
}
__device__ __forceinline__ uint32_t packbf(__nv_bfloat16 a, __nv_bfloat16 b){
    return (uint32_t)__bfloat16_as_ushort(a) | ((uint32_t)__bfloat16_as_ushort(b) << 16);
}
__device__ __forceinline__ float gelu_f(float x){
    float u = 0.7978845608028654f*(x + 0.044715f*x*x*x);
    return 0.5f*x*(1.f + tanhf(u));
}

// ---------- router ----------
__global__ void k_router(const float* __restrict__ x, const float* __restrict__ rw){
    int t = (blockIdx.x*blockDim.x + threadIdx.x) >> 5;
    int lane = threadIdx.x & 31;
    if (t >= Ntok) return;
    const float* xr = x + (size_t)t*Mdim;
    float acc[Ee];
#pragma unroll
    for (int e = 0; e < Ee; e++) acc[e] = 0.f;
    for (int m = lane; m < Mdim; m += 32){
        float xv = xr[m];
        const float4* r4 = (const float4*)(rw + m*Ee);
        float4 rA = r4[0], rB = r4[1];
        acc[0]=fmaf(xv,rA.x,acc[0]); acc[1]=fmaf(xv,rA.y,acc[1]);
        acc[2]=fmaf(xv,rA.z,acc[2]); acc[3]=fmaf(xv,rA.w,acc[3]);
        acc[4]=fmaf(xv,rB.x,acc[4]); acc[5]=fmaf(xv,rB.y,acc[5]);
        acc[6]=fmaf(xv,rB.z,acc[6]); acc[7]=fmaf(xv,rB.w,acc[7]);
    }
#pragma unroll
    for (int e = 0; e < Ee; e++)
#pragma unroll
        for (int o = 16; o > 0; o >>= 1)
            acc[e] += __shfl_xor_sync(0xffffffffu, acc[e], o);
    if (lane == 0){
        float mx = acc[0];
#pragma unroll
        for (int e = 1; e < Ee; e++) mx = fmaxf(mx, acc[e]);
        float p[Ee]; float sum = 0.f;
#pragma unroll
        for (int e = 0; e < Ee; e++){ p[e] = expf(acc[e]-mx); sum += p[e]; }
        float inv = 1.f/sum;
#pragma unroll
        for (int e = 0; e < Ee; e++) p[e] *= inv;
        int i1 = 0; float b1 = p[0];
#pragma unroll
        for (int e = 1; e < Ee; e++) if (p[e] > b1){ b1 = p[e]; i1 = e; }
        int i2 = -1; float b2 = -1.f;
#pragma unroll
        for (int e = 0; e < Ee; e++) if (e != i1 && p[e] > b2){ b2 = p[e]; i2 = e; }
        g_idx1[t]=i1; g_idx2[t]=i2; g_gate1[t]=b1; g_gate2[t]=b2;
    }
}

// ---------- capacity ----------
__global__ void k_capacity(){
    int g = blockIdx.x, tid = threadIdx.x;
    __shared__ int s_i1[Ss], s_i2[Ss], s_p1[Ss], s_p2[Ss];
    __shared__ int s_slot[Ee*Cc];
    __shared__ int s_cnt[Ee], s_m1c[Ee];
    for (int s = tid; s < Ss; s += blockDim.x){
        s_i1[s] = g_idx1[g*Ss+s]; s_i2[s] = g_idx2[g*Ss+s];
    }
    for (int i = tid; i < Ee*Cc; i += blockDim.x) s_slot[i] = -1;
    if (tid < Ee) s_cnt[tid] = 0;
    __syncthreads();
    if (tid == 0){
        for (int s = 0; s < Ss; s++){
            int e = s_i1[s]; int p = s_cnt[e]++;
            if (p < Cc){ s_p1[s] = p; s_slot[e*Cc+p] = s; } else s_p1[s] = -1;
        }
#pragma unroll
        for (int e = 0; e < Ee; e++){ s_m1c[e] = min(s_cnt[e], Cc); s_cnt[e] = 0; }
        for (int s = 0; s < Ss; s++){
            int e = s_i2[s]; int p = s_cnt[e]++ + s_m1c[e];
            if (p < Cc){ s_p2[s] = p; s_slot[e*Cc+p] = s; } else s_p2[s] = -1;
        }
    }
    __syncthreads();
    for (int i = tid; i < Ee*Cc; i += blockDim.x){
        int e = i/Cc, c = i%Cc;
        g_slotsrc[e*GCv + g*Cc + c] = s_slot[i];
    }
    for (int s = tid; s < Ss; s += blockDim.x){
        int p1 = s_p1[s], p2 = s_p2[s], e1 = s_i1[s], e2 = s_i2[s];
        g_tokinfo[g*Ss+s] = make_int2(p1 >= 0 ? e1*GCv + g*Cc + p1 : -1,
                                      p2 >= 0 ? e2*GCv + g*Cc + p2 : -1);
    }
}

// ---------- splitT body ----------
__device__ __forceinline__ void splitT_body(const float* __restrict__ src,
                                            __nv_bfloat16* __restrict__ dhi,
                                            __nv_bfloat16* __restrict__ dlo,
                                            int e, int r0, int c0,
                                            int R, int C, int Cp, int Rp, int tid){
    __shared__ float t[32][33];
    int tx = tid & 31, ty = tid >> 5;
    const float* s = src + (size_t)e*R*C;
#pragma unroll
    for (int i = 0; i < 4; i++){
        int rr = r0+ty+i*8, cc = c0+tx;
        t[ty+i*8][tx] = (rr < R && cc < C) ? s[(size_t)rr*C+cc] : 0.f;
    }
    __syncthreads();
    size_t dbase = (size_t)e*Cp*Rp;
#pragma unroll
    for (int i = 0; i < 4; i++){
        int dr = c0+ty+i*8, dc = r0+tx;
        __nv_bfloat16 h,l; split1(t[tx][ty+i*8], h, l);
        dhi[dbase + (size_t)dr*Rp + dc] = h;
        dlo[dbase + (size_t)dr*Rp + dc] = l;
    }
}

// ---------- fused prep ----------
#define NGATH (Ee*GCv)
#define NSPL  ((Mdim/32)*(Hp/32)*Ee)
__global__ void k_prep(const float* __restrict__ x,
                       const float* __restrict__ w0,
                       const float* __restrict__ w1){
    int b = blockIdx.x;
    int tid = threadIdx.x;
    if (b < NGATH){
        int row = b;
        int g = (row % GCv) / Cc;
        int src = g_slotsrc[row];
        float4 v = make_float4(0.f,0.f,0.f,0.f);
        if (src >= 0) v = ((const float4*)(x + (size_t)(g*Ss+src)*Mdim))[tid];
        __nv_bfloat16 h0,l0,h1,l1,h2,l2,h3,l3;
        split1(v.x,h0,l0); split1(v.y,h1,l1); split1(v.z,h2,l2); split1(v.w,h3,l3);
        ((uint2*)(g_a_hi + (size_t)row*Mdim))[tid] = make_uint2(packbf(h0,h1), packbf(h2,h3));
        ((uint2*)(g_a_lo + (size_t)row*Mdim))[tid] = make_uint2(packbf(l0,l1), packbf(l2,l3));
    } else {
        int b2 = b - NGATH;
        int which = b2 / NSPL;
        int r = b2 % NSPL;
        int bx = r % (Mdim/32);
        int by = (r / (Mdim/32)) % (Hp/32);
        int e  = r / ((Mdim/32)*(Hp/32));
        const float* src = which ? w1 : w0;
        __nv_bfloat16* dhi = which ? g_w1t_hi : g_w0t_hi;
        __nv_bfloat16* dlo = which ? g_w1t_lo : g_w0t_lo;
        splitT_body(src, dhi, dlo, e, bx*32, by*32, Mdim, Hh, Hp, Mdim, tid);
    }
}

// ---------- splitT for wo ----------
__global__ void k_splitT_wo(const float* __restrict__ wo){
    int bx = blockIdx.x, by = blockIdx.y, e = blockIdx.z;
    splitT_body(wo, g_wot_hi, g_wot_lo, e, bx*32, by*32, Hh, Mdim, Mdim, Hp, threadIdx.x);
}

#define ROWB    80
#define MATB_A  10240       // 128 rows x 80B
#define MATB_B  5120        // 64 rows x 80B
#define STG     (2*MATB_A + 2*MATB_B)   // 30720 per stage

// ---------- unified HMMA GEMM, 2 CTAs/SM ----------
// CTA tile 128(M) x 64(N); 8 warps as 4(M) x 2(N); warp tile 32x32 (2x4 m16n8, 32 accums)
// WHICH: 0 = a x w0t -> g_acc0
//        1 = a x w1t -> gelu(g_acc0)*d -> hid hi/lo
//        2 = hid x wot -> g_expout
template<int WHICH>
__global__ void __launch_bounds__(256, 2) k_mma(){
    constexpr int K = (WHICH == 2) ? Hp : Mdim;
    constexpr int N = (WHICH == 2) ? Mdim : Hp;
    constexpr int NKS = K / 32;

    const __nv_bfloat16* Ah = (WHICH==2) ? g_hid_hi : g_a_hi;
    const __nv_bfloat16* Al = (WHICH==2) ? g_hid_lo : g_a_lo;
    const __nv_bfloat16* Bh = (WHICH==0) ? g_w0t_hi : (WHICH==1) ? g_w1t_hi : g_wot_hi;
    const __nv_bfloat16* Bl = (WHICH==0) ? g_w0t_lo : (WHICH==1) ? g_w1t_lo : g_wot_lo;

    extern __shared__ __align__(128) char smem[];
    const uint32_t sb = s2u(smem);

    const int tid  = threadIdx.x;
    const int lane = tid & 31;
    const int wrp  = tid >> 5;
    const int wm   = (wrp >> 1) * 32;      // 4 warps in M
    const int wn   = (wrp & 1) * 32;       // 2 warps in N
    const int e  = blockIdx.z;
    const int bm = blockIdx.y * 128;
    const int bn = blockIdx.x * 64;

    const char* pAh = (const char*)(Ah + ((size_t)e*GCv + bm)*K);
    const char* pAl = (const char*)(Al + ((size_t)e*GCv + bm)*K);
    const char* pBh = (const char*)(Bh + ((size_t)e*N   + bn)*K);
    const char* pBl = (const char*)(Bl + ((size_t)e*N   + bn)*K);

    // A: 512 chunks per matrix -> 2/thread; B: 256 chunks -> 1/thread
    const int rb0 = tid >> 2,  qb0 = (tid & 3)*16;

    auto load_stage = [&](int ks, int buf){
        uint32_t s = sb + buf*STG;
        size_t ko = (size_t)ks * 64;
#pragma unroll
        for (int it = 0; it < 2; it++){
            int ci = tid*2 + it;
            int r = ci >> 2, q = (ci & 3)*16;
            cpa16(s + r*ROWB + q,          pAh + (size_t)r*(K*2) + ko + q);
            cpa16(s + MATB_A + r*ROWB + q, pAl + (size_t)r*(K*2) + ko + q);
        }
        uint32_t sB = s + 2*MATB_A;
        cpa16(sB + rb0*ROWB + qb0,          pBh + (size_t)rb0*(K*2) + ko + qb0);
        cpa16(sB + MATB_B + rb0*ROWB + qb0, pBl + (size_t)rb0*(K*2) + ko + qb0);
        CP_COMMIT();
    };

    float d[2][4][4];
#pragma unroll
    for (int i = 0; i < 2; i++)
#pragma unroll
        for (int j = 0; j < 4; j++)
#pragma unroll
            for (int q = 0; q < 4; q++) d[i][j][q] = 0.f;

    load_stage(0, 0);
    load_stage(1, 1);
    load_stage(2, 2);

    for (int ks = 0; ks < NKS; ks++){
        int buf = ks - (ks/3)*3;
        if (ks < NKS-2)       CP_WAIT2();
        else if (ks == NKS-2) CP_WAIT1();
        else                  CP_WAIT0();
        __syncthreads();
        uint32_t s0 = sb + buf*STG;
#pragma unroll
        for (int kk = 0; kk < 2; kk++){
            uint32_t ah[2][4], al[2][4], bh[4][2], bl[4][2];
#pragma unroll
            for (int mt = 0; mt < 2; mt++){
                uint32_t ad = s0 + (uint32_t)(wm + mt*16 + (lane & 15))*ROWB
                                 + (uint32_t)(kk*16 + (lane >> 4)*8)*2;
                LDSM4(ah[mt], ad);
                LDSM4(al[mt], ad + MATB_A);
            }
#pragma unroll
            for (int nt = 0; nt < 4; nt++){
                uint32_t bd = s0 + 2*MATB_A + (uint32_t)(wn + nt*8 + (lane & 7))*ROWB
                                 + (uint32_t)(kk*16 + ((lane >> 3) & 1)*8)*2;
                LDSM2(bh[nt], bd);
                LDSM2(bl[nt], bd + MATB_B);
            }
#pragma unroll
            for (int mt = 0; mt < 2; mt++)
#pragma unroll
                for (int nt = 0; nt < 4; nt++){
                    MMA_BF16(d[mt][nt], ah[mt], bh[nt]);
                    MMA_BF16(d[mt][nt], ah[mt], bl[nt]);
                    MMA_BF16(d[mt][nt], al[mt], bh[nt]);
                }
        }
        __syncthreads();
        if (ks + 3 < NKS) load_stage(ks + 3, buf);
    }

    const int rb = bm + wm + (lane >> 2);
    const int cb = bn + wn + 2*(lane & 3);
#pragma unroll
    for (int mt = 0; mt < 2; mt++)
#pragma unroll
        for (int nt = 0; nt < 4; nt++)
#pragma unroll
            for (int h = 0; h < 2; h++){
                int row = rb + mt*16 + h*8;
                int col = cb + nt*8;
                float va = d[mt][nt][h*2+0], vb = d[mt][nt][h*2+1];
                if (WHICH == 0){
                    size_t idx = ((size_t)e*GCv + row)*(size_t)Hp + col;
                    *(float2*)(g_acc0 + idx) = make_float2(va, vb);
                } else if (WHICH == 1){
                    size_t idx = ((size_t)e*GCv + row)*(size_t)Hp + col;
                    float2 a0 = *(const float2*)(g_acc0 + idx);
                    float ha = gelu_f(a0.x)*va, hb = gelu_f(a0.y)*vb;
                    __nv_bfloat16 ahh, alo, bhh, blo;
                    split1(ha, ahh, alo); split1(hb, bhh, blo);
                    *(uint32_t*)(g_hid_hi + idx) = packbf(ahh, bhh);
                    *(uint32_t*)(g_hid_lo + idx) = packbf(alo, blo);
                } else {
                    size_t idx = ((size_t)e*GCv + row)*(size_t)Mdim + col;
                    *(float2*)(g_expout + idx) = make_float2(va, vb);
                }
            }
}

// ---------- combine ----------
__global__ void k_combine(float* __restrict__ out){
    int t = blockIdx.x, i = threadIdx.x;
    int2 info = g_tokinfo[t];
    float4 acc = make_float4(0.f,0.f,0.f,0.f);
    if (info.x >= 0){
        float gv = g_gate1[t];
        float4 v = ((const float4*)(g_expout + (size_t)info.x*Mdim))[i];
        acc.x += gv*v.x; acc.y += gv*v.y; acc.z += gv*v.z; acc.w += gv*v.w;
    }
    if (info.y >= 0){
        float gv = g_gate2[t];
        float4 v = ((const float4*)(g_expout + (size_t)info.y*Mdim))[i];
        acc.x += gv*v.x; acc.y += gv*v.y; acc.z += gv*v.z; acc.w += gv*v.w;
    }
    ((float4*)(out + (size_t)t*Mdim))[i] = acc;
}

// ---------- launch ----------
extern "C" void kernel_launch(void* const* d_in, const int* in_sizes, int n_in,
                              void* d_out, int out_size){
    const float* x  = (const float*)d_in[0];
    const float* rw = (const float*)d_in[1];
    const float* w0 = (const float*)d_in[2];
    const float* w1 = (const float*)d_in[3];
    const float* wo = (const float*)d_in[4];
    float* out = (float*)d_out;

    static bool attr_done = false;
    if (!attr_done){
        cudaFuncSetAttribute(k_mma<0>, cudaFuncAttributeMaxDynamicSharedMemorySize, 3*STG);
        cudaFuncSetAttribute(k_mma<1>, cudaFuncAttributeMaxDynamicSharedMemorySize, 3*STG);
        cudaFuncSetAttribute(k_mma<2>, cudaFuncAttributeMaxDynamicSharedMemorySize, 3*STG);
        attr_done = true;
    }

    // k_mma<0> is the 4th launch (the one ncu captures)
    k_router<<<Ntok/8, 256>>>(x, rw);                                   // 1
    k_capacity<<<Gg, 256>>>();                                          // 2
    k_prep<<<NGATH + 2*NSPL, 256>>>(x, w0, w1);                         // 3
    k_mma<0><<<dim3(Hp/64,  GCv/128, Ee), 256, 3*STG>>>();              // 4 <- profiled
    k_mma<1><<<dim3(Hp/64,  GCv/128, Ee), 256, 3*STG>>>();              // 5
    k_splitT_wo<<<dim3(Hh/32 + 1, Mdim/32, Ee), 256>>>(wo);             // 6
    k_mma<2><<<dim3(Mdim/64, GCv/128, Ee), 256, 3*STG>>>();             // 7
    k_combine<<<Ntok, 256>>>(out);                                      // 8
}

// round 9
// speedup vs baseline: 1.1443x; 1.1443x over previous
#include <cuda_runtime.h>
#include <cuda_bf16.h>
#include <math.h>
#include <stdint.h>

#define Gg 8
#define Ee 8
#define Ss 1024
#define Cc 256
#define Mdim 1024
#define Hh 5464
#define Hp 5504
#define Ntok (Gg*Ss)
#define GCv (Gg*Cc)

// ---------------- device scratch ----------------
__device__ __align__(256) __nv_bfloat16 g_a_hi [(size_t)Ee*GCv*Mdim];
__device__ __align__(256) __nv_bfloat16 g_a_lo [(size_t)Ee*GCv*Mdim];
__device__ __align__(256) __nv_bfloat16 g_w0t_hi[(size_t)Ee*Hp*Mdim];
__device__ __align__(256) __nv_bfloat16 g_w0t_lo[(size_t)Ee*Hp*Mdim];
__device__ __align__(256) __nv_bfloat16 g_w1t_hi[(size_t)Ee*Hp*Mdim];
__device__ __align__(256) __nv_bfloat16 g_w1t_lo[(size_t)Ee*Hp*Mdim];
__device__ __align__(256) __nv_bfloat16 g_wot_hi[(size_t)Ee*Mdim*Hp];
__device__ __align__(256) __nv_bfloat16 g_wot_lo[(size_t)Ee*Mdim*Hp];
__device__ __align__(256) __nv_bfloat16 g_hid_hi[(size_t)Ee*GCv*Hp];
__device__ __align__(256) __nv_bfloat16 g_hid_lo[(size_t)Ee*GCv*Hp];
__device__ __align__(256) float g_acc0  [(size_t)Ee*GCv*Hp];
__device__ __align__(256) float g_expout[(size_t)Ee*GCv*Mdim];
__device__ int   g_idx1[Ntok];
__device__ int   g_idx2[Ntok];
__device__ float g_gate1[Ntok];
__device__ float g_gate2[Ntok];
__device__ int   g_slotsrc[Ee*GCv];
__device__ int2  g_tokinfo[Ntok];

// ---------------- helpers ----------------
__device__ __forceinline__ uint32_t s2u(const void* p){
    uint32_t a; asm("{ .reg .u64 t; cvta.to.shared.u64 t, %1; cvt.u32.u64 %0, t; }":"=r"(a):"l"(p)); return a;
}
__device__ __forceinline__ void cpa16(uint32_t d, const void* s){
    asm volatile("cp.async.cg.shared.global [%0], [%1], 16;"::"r"(d),"l"(s));
}
#define CP_COMMIT() asm volatile("cp.async.commit_group;":::"memory")
#define CP_WAIT1()  asm volatile("cp.async.wait_group 1;":::"memory")
#define CP_WAIT0()  asm volatile("cp.async.wait_group 0;":::"memory")

#define LDSM4(R, addr) \
    asm volatile("ldmatrix.sync.aligned.m8n8.x4.shared.b16 {%0,%1,%2,%3}, [%4];" \
        : "=r"((R)[0]),"=r"((R)[1]),"=r"((R)[2]),"=r"((R)[3]) : "r"(addr))
#define LDSM2(R, addr) \
    asm volatile("ldmatrix.sync.aligned.m8n8.x2.shared.b16 {%0,%1}, [%2];" \
        : "=r"((R)[0]),"=r"((R)[1]) : "r"(addr))
#define MMA_BF16(D, A, B) \
    asm volatile("mma.sync.aligned.m16n8k16.row.col.f32.bf16.bf16.f32 " \
        "{%0,%1,%2,%3}, {%4,%5,%6,%7}, {%8,%9}, {%0,%1,%2,%3};" \
        : "+f"((D)[0]),"+f"((D)[1]),"+f"((D)[2]),"+f"((D)[3]) \
        : "r"((A)[0]),"r"((A)[1]),"r"((A)[2]),"r"((A)[3]), "r"((B)[0]),"r"((B)[1]))

__device__ __forceinline__ void split1(float a, __nv_bfloat16& h, __nv_bfloat16& l){
    h = __float2bfloat16(a); l = __float2bfloat16(a - __bfloat162float(h));
}
__device__ __forceinline__ uint32_t packbf(__nv_bfloat16 a, __nv_bfloat16 b){
    return (uint32_t)__bfloat16_as_ushort(a) | ((uint32_t)__bfloat16_as_ushort(b) << 16);
}
__device__ __forceinline__ float gelu_f(float x){
    float u = 0.7978845608028654f*(x + 0.044715f*x*x*x);
    return 0.5f*x*(1.f + tanhf(u));
}

// ---------- router ----------
__global__ void k_router(const float* __restrict__ x, const float* __restrict__ rw){
    int t = (blockIdx.x*blockDim.x + threadIdx.x) >> 5;
    int lane = threadIdx.x & 31;
    if (t >= Ntok) return;
    const float* xr = x + (size_t)t*Mdim;
    float acc[Ee];
#pragma unroll
    for (int e = 0; e < Ee; e++) acc[e] = 0.f;
    for (int m = lane; m < Mdim; m += 32){
        float xv = xr[m];
        const float4* r4 = (const float4*)(rw + m*Ee);
        float4 rA = r4[0], rB = r4[1];
        acc[0]=fmaf(xv,rA.x,acc[0]); acc[1]=fmaf(xv,rA.y,acc[1]);
        acc[2]=fmaf(xv,rA.z,acc[2]); acc[3]=fmaf(xv,rA.w,acc[3]);
        acc[4]=fmaf(xv,rB.x,acc[4]); acc[5]=fmaf(xv,rB.y,acc[5]);
        acc[6]=fmaf(xv,rB.z,acc[6]); acc[7]=fmaf(xv,rB.w,acc[7]);
    }
#pragma unroll
    for (int e = 0; e < Ee; e++)
#pragma unroll
        for (int o = 16; o > 0; o >>= 1)
            acc[e] += __shfl_xor_sync(0xffffffffu, acc[e], o);
    if (lane == 0){
        float mx = acc[0];
#pragma unroll
        for (int e = 1; e < Ee; e++) mx = fmaxf(mx, acc[e]);
        float p[Ee]; float sum = 0.f;
#pragma unroll
        for (int e = 0; e < Ee; e++){ p[e] = expf(acc[e]-mx); sum += p[e]; }
        float inv = 1.f/sum;
#pragma unroll
        for (int e = 0; e < Ee; e++) p[e] *= inv;
        int i1 = 0; float b1 = p[0];
#pragma unroll
        for (int e = 1; e < Ee; e++) if (p[e] > b1){ b1 = p[e]; i1 = e; }
        int i2 = -1; float b2 = -1.f;
#pragma unroll
        for (int e = 0; e < Ee; e++) if (e != i1 && p[e] > b2){ b2 = p[e]; i2 = e; }
        g_idx1[t]=i1; g_idx2[t]=i2; g_gate1[t]=b1; g_gate2[t]=b2;
    }
}

// ---------- capacity ----------
__global__ void k_capacity(){
    int g = blockIdx.x, tid = threadIdx.x;
    __shared__ int s_i1[Ss], s_i2[Ss], s_p1[Ss], s_p2[Ss];
    __shared__ int s_slot[Ee*Cc];
    __shared__ int s_cnt[Ee], s_m1c[Ee];
    for (int s = tid; s < Ss; s += blockDim.x){
        s_i1[s] = g_idx1[g*Ss+s]; s_i2[s] = g_idx2[g*Ss+s];
    }
    for (int i = tid; i < Ee*Cc; i += blockDim.x) s_slot[i] = -1;
    if (tid < Ee) s_cnt[tid] = 0;
    __syncthreads();
    if (tid == 0){
        for (int s = 0; s < Ss; s++){
            int e = s_i1[s]; int p = s_cnt[e]++;
            if (p < Cc){ s_p1[s] = p; s_slot[e*Cc+p] = s; } else s_p1[s] = -1;
        }
#pragma unroll
        for (int e = 0; e < Ee; e++){ s_m1c[e] = min(s_cnt[e], Cc); s_cnt[e] = 0; }
        for (int s = 0; s < Ss; s++){
            int e = s_i2[s]; int p = s_cnt[e]++ + s_m1c[e];
            if (p < Cc){ s_p2[s] = p; s_slot[e*Cc+p] = s; } else s_p2[s] = -1;
        }
    }
    __syncthreads();
    for (int i = tid; i < Ee*Cc; i += blockDim.x){
        int e = i/Cc, c = i%Cc;
        g_slotsrc[e*GCv + g*Cc + c] = s_slot[i];
    }
    for (int s = tid; s < Ss; s += blockDim.x){
        int p1 = s_p1[s], p2 = s_p2[s], e1 = s_i1[s], e2 = s_i2[s];
        g_tokinfo[g*Ss+s] = make_int2(p1 >= 0 ? e1*GCv + g*Cc + p1 : -1,
                                      p2 >= 0 ? e2*GCv + g*Cc + p2 : -1);
    }
}

// ---------- splitT body ----------
__device__ __forceinline__ void splitT_body(const float* __restrict__ src,
                                            __nv_bfloat16* __restrict__ dhi,
                                            __nv_bfloat16* __restrict__ dlo,
                                            int e, int r0, int c0,
                                            int R, int C, int Cp, int Rp, int tid){
    __shared__ float t[32][33];
    int tx = tid & 31, ty = tid >> 5;
    const float* s = src + (size_t)e*R*C;
#pragma unroll
    for (int i = 0; i < 4; i++){
        int rr = r0+ty+i*8, cc = c0+tx;
        t[ty+i*8][tx] = (rr < R && cc < C) ? s[(size_t)rr*C+cc] : 0.f;
    }
    __syncthreads();
    size_t dbase = (size_t)e*Cp*Rp;
#pragma unroll
    for (int i = 0; i < 4; i++){
        int dr = c0+ty+i*8, dc = r0+tx;
        __nv_bfloat16 h,l; split1(t[tx][ty+i*8], h, l);
        dhi[dbase + (size_t)dr*Rp + dc] = h;
        dlo[dbase + (size_t)dr*Rp + dc] = l;
    }
}

// ---------- fused prep ----------
#define NGATH (Ee*GCv)
#define NSPL  ((Mdim/32)*(Hp/32)*Ee)
__global__ void k_prep(const float* __restrict__ x,
                       const float* __restrict__ w0,
                       const float* __restrict__ w1){
    int b = blockIdx.x;
    int tid = threadIdx.x;
    if (b < NGATH){
        int row = b;
        int g = (row % GCv) / Cc;
        int src = g_slotsrc[row];
        float4 v = make_float4(0.f,0.f,0.f,0.f);
        if (src >= 0) v = ((const float4*)(x + (size_t)(g*Ss+src)*Mdim))[tid];
        __nv_bfloat16 h0,l0,h1,l1,h2,l2,h3,l3;
        split1(v.x,h0,l0); split1(v.y,h1,l1); split1(v.z,h2,l2); split1(v.w,h3,l3);
        ((uint2*)(g_a_hi + (size_t)row*Mdim))[tid] = make_uint2(packbf(h0,h1), packbf(h2,h3));
        ((uint2*)(g_a_lo + (size_t)row*Mdim))[tid] = make_uint2(packbf(l0,l1), packbf(l2,l3));
    } else {
        int b2 = b - NGATH;
        int which = b2 / NSPL;
        int r = b2 % NSPL;
        int bx = r % (Mdim/32);
        int by = (r / (Mdim/32)) % (Hp/32);
        int e  = r / ((Mdim/32)*(Hp/32));
        const float* src = which ? w1 : w0;
        __nv_bfloat16* dhi = which ? g_w1t_hi : g_w0t_hi;
        __nv_bfloat16* dlo = which ? g_w1t_lo : g_w0t_lo;
        splitT_body(src, dhi, dlo, e, bx*32, by*32, Mdim, Hh, Hp, Mdim, tid);
    }
}

// ---------- splitT for wo ----------
__global__ void k_splitT_wo(const float* __restrict__ wo){
    int bx = blockIdx.x, by = blockIdx.y, e = blockIdx.z;
    splitT_body(wo, g_wot_hi, g_wot_lo, e, bx*32, by*32, Hh, Mdim, Mdim, Hp, threadIdx.x);
}

#define ROWB  80
#define MATB  10240                  // 128 rows x 80B
#define STG   (4*MATB)               // A_hi A_lo B_hi B_lo = 40960 per stage

// ---------- unified HMMA GEMM: 512 threads, tile 128x128, warp 32x32 ----------
// 16 warps as 4(M) x 4(N). 3-stage cp.async pipeline, ONE sync per k-step.
// WHICH: 0 = a x w0t -> g_acc0
//        1 = a x w1t -> gelu(g_acc0)*d -> hid hi/lo
//        2 = hid x wot -> g_expout
template<int WHICH>
__global__ void __launch_bounds__(512, 1) k_mma(){
    constexpr int K = (WHICH == 2) ? Hp : Mdim;
    constexpr int N = (WHICH == 2) ? Mdim : Hp;
    constexpr int NKS = K / 32;

    const __nv_bfloat16* Ah = (WHICH==2) ? g_hid_hi : g_a_hi;
    const __nv_bfloat16* Al = (WHICH==2) ? g_hid_lo : g_a_lo;
    const __nv_bfloat16* Bh = (WHICH==0) ? g_w0t_hi : (WHICH==1) ? g_w1t_hi : g_wot_hi;
    const __nv_bfloat16* Bl = (WHICH==0) ? g_w0t_lo : (WHICH==1) ? g_w1t_lo : g_wot_lo;

    extern __shared__ __align__(128) char smem[];
    const uint32_t sb = s2u(smem);

    const int tid  = threadIdx.x;
    const int lane = tid & 31;
    const int wrp  = tid >> 5;
    const int wm   = (wrp >> 2) * 32;      // 4 warp-rows
    const int wn   = (wrp & 3) * 32;       // 4 warp-cols
    const int e  = blockIdx.z;
    const int bm = blockIdx.y * 128;
    const int bn = blockIdx.x * 128;

    const char* pAh = (const char*)(Ah + ((size_t)e*GCv + bm)*K);
    const char* pAl = (const char*)(Al + ((size_t)e*GCv + bm)*K);
    const char* pBh = (const char*)(Bh + ((size_t)e*N   + bn)*K);
    const char* pBl = (const char*)(Bl + ((size_t)e*N   + bn)*K);

    // 512 chunks per matrix (128 rows x 4 x 16B): exactly 1 chunk/thread/matrix
    const int rc = tid >> 2, qc = (tid & 3)*16;

    auto load_stage = [&](int ks, int buf){
        uint32_t s = sb + buf*STG;
        size_t go = (size_t)rc*(K*2) + (size_t)ks*64 + qc;
        uint32_t so = (uint32_t)(rc*ROWB + qc);
        cpa16(s +          so, pAh + go);
        cpa16(s + MATB   + so, pAl + go);
        cpa16(s + 2*MATB + so, pBh + go);
        cpa16(s + 3*MATB + so, pBl + go);
        CP_COMMIT();
    };

    float d[2][4][4];
#pragma unroll
    for (int i = 0; i < 2; i++)
#pragma unroll
        for (int j = 0; j < 4; j++)
#pragma unroll
            for (int q = 0; q < 4; q++) d[i][j][q] = 0.f;

    load_stage(0, 0);
    load_stage(1, 1);

    for (int ks = 0; ks < NKS; ks++){
        if (ks < NKS-1) CP_WAIT1(); else CP_WAIT0();
        __syncthreads();
        // issue the next-next stage load early (overwrites buffer read 2 iters ago)
        if (ks + 2 < NKS) load_stage(ks + 2, (ks + 2) % 3);

        uint32_t s0 = sb + (ks % 3)*STG;
#pragma unroll
        for (int kk = 0; kk < 2; kk++){
            uint32_t ah[2][4], al[2][4], bh[4][2], bl[4][2];
#pragma unroll
            for (int mt = 0; mt < 2; mt++){
                uint32_t ad = s0 + (uint32_t)(wm + mt*16 + (lane & 15))*ROWB
                                 + (uint32_t)(kk*16 + (lane >> 4)*8)*2;
                LDSM4(ah[mt], ad);
                LDSM4(al[mt], ad + MATB);
            }
#pragma unroll
            for (int nt = 0; nt < 4; nt++){
                uint32_t bd = s0 + 2*MATB + (uint32_t)(wn + nt*8 + (lane & 7))*ROWB
                                 + (uint32_t)(kk*16 + ((lane >> 3) & 1)*8)*2;
                LDSM2(bh[nt], bd);
                LDSM2(bl[nt], bd + MATB);
            }
#pragma unroll
            for (int mt = 0; mt < 2; mt++)
#pragma unroll
                for (int nt = 0; nt < 4; nt++){
                    MMA_BF16(d[mt][nt], ah[mt], bh[nt]);
                    MMA_BF16(d[mt][nt], ah[mt], bl[nt]);
                    MMA_BF16(d[mt][nt], al[mt], bh[nt]);
                }
        }
    }

    const int rb = bm + wm + (lane >> 2);
    const int cb = bn + wn + 2*(lane & 3);
#pragma unroll
    for (int mt = 0; mt < 2; mt++)
#pragma unroll
        for (int nt = 0; nt < 4; nt++)
#pragma unroll
            for (int h = 0; h < 2; h++){
                int row = rb + mt*16 + h*8;
                int col = cb + nt*8;
                float va = d[mt][nt][h*2+0], vb = d[mt][nt][h*2+1];
                if (WHICH == 0){
                    size_t idx = ((size_t)e*GCv + row)*(size_t)Hp + col;
                    *(float2*)(g_acc0 + idx) = make_float2(va, vb);
                } else if (WHICH == 1){
                    size_t idx = ((size_t)e*GCv + row)*(size_t)Hp + col;
                    float2 a0 = *(const float2*)(g_acc0 + idx);
                    float ha = gelu_f(a0.x)*va, hb = gelu_f(a0.y)*vb;
                    __nv_bfloat16 ahh, alo, bhh, blo;
                    split1(ha, ahh, alo); split1(hb, bhh, blo);
                    *(uint32_t*)(g_hid_hi + idx) = packbf(ahh, bhh);
                    *(uint32_t*)(g_hid_lo + idx) = packbf(alo, blo);
                } else {
                    size_t idx = ((size_t)e*GCv + row)*(size_t)Mdim + col;
                    *(float2*)(g_expout + idx) = make_float2(va, vb);
                }
            }
}

// ---------- combine ----------
__global__ void k_combine(float* __restrict__ out){
    int t = blockIdx.x, i = threadIdx.x;
    int2 info = g_tokinfo[t];
    float4 acc = make_float4(0.f,0.f,0.f,0.f);
    if (info.x >= 0){
        float gv = g_gate1[t];
        float4 v = ((const float4*)(g_expout + (size_t)info.x*Mdim))[i];
        acc.x += gv*v.x; acc.y += gv*v.y; acc.z += gv*v.z; acc.w += gv*v.w;
    }
    if (info.y >= 0){
        float gv = g_gate2[t];
        float4 v = ((const float4*)(g_expout + (size_t)info.y*Mdim))[i];
        acc.x += gv*v.x; acc.y += gv*v.y; acc.z += gv*v.z; acc.w += gv*v.w;
    }
    ((float4*)(out + (size_t)t*Mdim))[i] = acc;
}

// ---------- launch ----------
extern "C" void kernel_launch(void* const* d_in, const int* in_sizes, int n_in,
                              void* d_out, int out_size){
    const float* x  = (const float*)d_in[0];
    const float* rw = (const float*)d_in[1];
    const float* w0 = (const float*)d_in[2];
    const float* w1 = (const float*)d_in[3];
    const float* wo = (const float*)d_in[4];
    float* out = (float*)d_out;

    static bool attr_done = false;
    if (!attr_done){
        cudaFuncSetAttribute(k_mma<0>, cudaFuncAttributeMaxDynamicSharedMemorySize, 3*STG);
        cudaFuncSetAttribute(k_mma<1>, cudaFuncAttributeMaxDynamicSharedMemorySize, 3*STG);
        cudaFuncSetAttribute(k_mma<2>, cudaFuncAttributeMaxDynamicSharedMemorySize, 3*STG);
        attr_done = true;
    }

    // k_mma<0> is the 4th launch (the one ncu captures)
    k_router<<<Ntok/8, 256>>>(x, rw);                                    // 1
    k_capacity<<<Gg, 256>>>();                                           // 2
    k_prep<<<NGATH + 2*NSPL, 256>>>(x, w0, w1);                          // 3
    k_mma<0><<<dim3(Hp/128,  GCv/128, Ee), 512, 3*STG>>>();              // 4 <- profiled
    k_mma<1><<<dim3(Hp/128,  GCv/128, Ee), 512, 3*STG>>>();              // 5
    k_splitT_wo<<<dim3(Hh/32 + 1, Mdim/32, Ee), 256>>>(wo);              // 6
    k_mma<2><<<dim3(Mdim/128, GCv/128, Ee), 512, 3*STG>>>();             // 7
    k_combine<<<Ntok, 256>>>(out);                                       // 8
}

// round 10
// speedup vs baseline: 2.6531x; 2.3185x over previous
#include <cuda_runtime.h>
#include <cuda_fp16.h>
#include <math.h>
#include <stdint.h>

#define Gg 8
#define Ee 8
#define Ss 1024
#define Cc 256
#define Mdim 1024
#define Hh 5464
#define Hp 5504
#define Ntok (Gg*Ss)
#define GCv (Gg*Cc)

// ---------------- device scratch (fp16 operands) ----------------
__device__ __align__(256) __half g_a  [(size_t)Ee*GCv*Mdim];
__device__ __align__(256) __half g_w0t[(size_t)Ee*Hp*Mdim];
__device__ __align__(256) __half g_w1t[(size_t)Ee*Hp*Mdim];
__device__ __align__(256) __half g_wot[(size_t)Ee*Mdim*Hp];
__device__ __align__(256) __half g_hid[(size_t)Ee*GCv*Hp];
__device__ __align__(256) float g_expout[(size_t)Ee*GCv*Mdim];
__device__ int   g_idx1[Ntok];
__device__ int   g_idx2[Ntok];
__device__ float g_gate1[Ntok];
__device__ float g_gate2[Ntok];
__device__ int   g_slotsrc[Ee*GCv];
__device__ int2  g_tokinfo[Ntok];

// ---------------- helpers ----------------
__device__ __forceinline__ uint32_t s2u(const void* p){
    uint32_t a; asm("{ .reg .u64 t; cvta.to.shared.u64 t, %1; cvt.u32.u64 %0, t; }":"=r"(a):"l"(p)); return a;
}
__device__ __forceinline__ void cpa16(uint32_t d, const void* s){
    asm volatile("cp.async.cg.shared.global [%0], [%1], 16;"::"r"(d),"l"(s));
}
#define CP_COMMIT() asm volatile("cp.async.commit_group;":::"memory")
#define CP_WAIT1()  asm volatile("cp.async.wait_group 1;":::"memory")
#define CP_WAIT0()  asm volatile("cp.async.wait_group 0;":::"memory")

#define LDSM4(R, addr) \
    asm volatile("ldmatrix.sync.aligned.m8n8.x4.shared.b16 {%0,%1,%2,%3}, [%4];" \
        : "=r"((R)[0]),"=r"((R)[1]),"=r"((R)[2]),"=r"((R)[3]) : "r"(addr))
#define LDSM2(R, addr) \
    asm volatile("ldmatrix.sync.aligned.m8n8.x2.shared.b16 {%0,%1}, [%2];" \
        : "=r"((R)[0]),"=r"((R)[1]) : "r"(addr))
#define MMA_F16(D, A, B) \
    asm volatile("mma.sync.aligned.m16n8k16.row.col.f32.f16.f16.f32 " \
        "{%0,%1,%2,%3}, {%4,%5,%6,%7}, {%8,%9}, {%0,%1,%2,%3};" \
        : "+f"((D)[0]),"+f"((D)[1]),"+f"((D)[2]),"+f"((D)[3]) \
        : "r"((A)[0]),"r"((A)[1]),"r"((A)[2]),"r"((A)[3]), "r"((B)[0]),"r"((B)[1]))

__device__ __forceinline__ uint32_t packh(float a, float b){
    __half2 h = __floats2half2_rn(a, b);
    return *(uint32_t*)&h;
}
__device__ __forceinline__ float gelu_f(float x){
    float u = 0.7978845608028654f*(x + 0.044715f*x*x*x);
    return 0.5f*x*(1.f + tanhf(u));
}

// ---------- router ----------
__global__ void k_router(const float* __restrict__ x, const float* __restrict__ rw){
    int t = (blockIdx.x*blockDim.x + threadIdx.x) >> 5;
    int lane = threadIdx.x & 31;
    if (t >= Ntok) return;
    const float* xr = x + (size_t)t*Mdim;
    float acc[Ee];
#pragma unroll
    for (int e = 0; e < Ee; e++) acc[e] = 0.f;
    for (int m = lane; m < Mdim; m += 32){
        float xv = xr[m];
        const float4* r4 = (const float4*)(rw + m*Ee);
        float4 rA = r4[0], rB = r4[1];
        acc[0]=fmaf(xv,rA.x,acc[0]); acc[1]=fmaf(xv,rA.y,acc[1]);
        acc[2]=fmaf(xv,rA.z,acc[2]); acc[3]=fmaf(xv,rA.w,acc[3]);
        acc[4]=fmaf(xv,rB.x,acc[4]); acc[5]=fmaf(xv,rB.y,acc[5]);
        acc[6]=fmaf(xv,rB.z,acc[6]); acc[7]=fmaf(xv,rB.w,acc[7]);
    }
#pragma unroll
    for (int e = 0; e < Ee; e++)
#pragma unroll
        for (int o = 16; o > 0; o >>= 1)
            acc[e] += __shfl_xor_sync(0xffffffffu, acc[e], o);
    if (lane == 0){
        float mx = acc[0];
#pragma unroll
        for (int e = 1; e < Ee; e++) mx = fmaxf(mx, acc[e]);
        float p[Ee]; float sum = 0.f;
#pragma unroll
        for (int e = 0; e < Ee; e++){ p[e] = expf(acc[e]-mx); sum += p[e]; }
        float inv = 1.f/sum;
#pragma unroll
        for (int e = 0; e < Ee; e++) p[e] *= inv;
        int i1 = 0; float b1 = p[0];
#pragma unroll
        for (int e = 1; e < Ee; e++) if (p[e] > b1){ b1 = p[e]; i1 = e; }
        int i2 = -1; float b2 = -1.f;
#pragma unroll
        for (int e = 0; e < Ee; e++) if (e != i1 && p[e] > b2){ b2 = p[e]; i2 = e; }
        g_idx1[t]=i1; g_idx2[t]=i2; g_gate1[t]=b1; g_gate2[t]=b2;
    }
}

// ---------- capacity ----------
__global__ void k_capacity(){
    int g = blockIdx.x, tid = threadIdx.x;
    __shared__ int s_i1[Ss], s_i2[Ss], s_p1[Ss], s_p2[Ss];
    __shared__ int s_slot[Ee*Cc];
    __shared__ int s_cnt[Ee], s_m1c[Ee];
    for (int s = tid; s < Ss; s += blockDim.x){
        s_i1[s] = g_idx1[g*Ss+s]; s_i2[s] = g_idx2[g*Ss+s];
    }
    for (int i = tid; i < Ee*Cc; i += blockDim.x) s_slot[i] = -1;
    if (tid < Ee) s_cnt[tid] = 0;
    __syncthreads();
    if (tid == 0){
        for (int s = 0; s < Ss; s++){
            int e = s_i1[s]; int p = s_cnt[e]++;
            if (p < Cc){ s_p1[s] = p; s_slot[e*Cc+p] = s; } else s_p1[s] = -1;
        }
#pragma unroll
        for (int e = 0; e < Ee; e++){ s_m1c[e] = min(s_cnt[e], Cc); s_cnt[e] = 0; }
        for (int s = 0; s < Ss; s++){
            int e = s_i2[s]; int p = s_cnt[e]++ + s_m1c[e];
            if (p < Cc){ s_p2[s] = p; s_slot[e*Cc+p] = s; } else s_p2[s] = -1;
        }
    }
    __syncthreads();
    for (int i = tid; i < Ee*Cc; i += blockDim.x){
        int e = i/Cc, c = i%Cc;
        g_slotsrc[e*GCv + g*Cc + c] = s_slot[i];
    }
    for (int s = tid; s < Ss; s += blockDim.x){
        int p1 = s_p1[s], p2 = s_p2[s], e1 = s_i1[s], e2 = s_i2[s];
        g_tokinfo[g*Ss+s] = make_int2(p1 >= 0 ? e1*GCv + g*Cc + p1 : -1,
                                      p2 >= 0 ? e2*GCv + g*Cc + p2 : -1);
    }
}

// ---------- transpose+convert body: src[E][R][C] -> dst[E][Cp][Rp] (fp16, zero-padded) ----------
__device__ __forceinline__ void splitT_body(const float* __restrict__ src,
                                            __half* __restrict__ dst,
                                            int e, int r0, int c0,
                                            int R, int C, int Cp, int Rp, int tid){
    __shared__ float t[32][33];
    int tx = tid & 31, ty = tid >> 5;
    const float* s = src + (size_t)e*R*C;
#pragma unroll
    for (int i = 0; i < 4; i++){
        int rr = r0+ty+i*8, cc = c0+tx;
        t[ty+i*8][tx] = (rr < R && cc < C) ? s[(size_t)rr*C+cc] : 0.f;
    }
    __syncthreads();
    size_t dbase = (size_t)e*Cp*Rp;
#pragma unroll
    for (int i = 0; i < 4; i++){
        int dr = c0+ty+i*8, dc = r0+tx;
        if (dr < Cp && dc < Rp)
            dst[dbase + (size_t)dr*Rp + dc] = __float2half_rn(t[tx][ty+i*8]);
    }
}

// ---------- fused prep: gather + convert w0,w1,wo ----------
#define NGATH (Ee*GCv)                          // 16384
#define NSPL  (32*172*Ee)                        // w0/w1: (Mdim/32)x(Hp/32)xE = 44032
#define NSPLW (172*32*Ee)                        // wo:    (Hp/32)x(Mdim/32)xE = 44032
__global__ void k_prep(const float* __restrict__ x,
                       const float* __restrict__ w0,
                       const float* __restrict__ w1,
                       const float* __restrict__ wo){
    int b = blockIdx.x;
    int tid = threadIdx.x;
    if (b < NGATH){
        int row = b;
        int g = (row % GCv) / Cc;
        int src = g_slotsrc[row];
        float4 v = make_float4(0.f,0.f,0.f,0.f);
        if (src >= 0) v = ((const float4*)(x + (size_t)(g*Ss+src)*Mdim))[tid];
        ((uint2*)(g_a + (size_t)row*Mdim))[tid] = make_uint2(packh(v.x,v.y), packh(v.z,v.w));
        return;
    }
    int b2 = b - NGATH;
    if (b2 < 2*NSPL){
        int which = b2 / NSPL;
        int r = b2 % NSPL;
        int bx = r % 32;                 // r0/32 over Mdim rows
        int by = (r / 32) % 172;         // c0/32 over Hp cols
        int e  = r / (32*172);
        splitT_body(which ? w1 : w0, which ? g_w1t : g_w0t,
                    e, bx*32, by*32, Mdim, Hh, Hp, Mdim, tid);
    } else {
        int r = b2 - 2*NSPL;
        int bx = r % 172;                // r0/32 over Hp rows (covers K pad)
        int by = (r / 172) % 32;         // c0/32 over Mdim cols
        int e  = r / (172*32);
        splitT_body(wo, g_wot, e, bx*32, by*32, Hh, Mdim, Mdim, Hp, tid);
    }
}

#define ROWB  80
#define MATB  10240                  // 128 rows x 80B

// ---------- fused GEMM1 (fp16): A x {W0,W1} -> gelu*mul -> hid fp16 ----------
// 512 threads, CTA tile 128x128, 16 warps 4x4, warp tile 32x32, dual accum.
#define STG1 (3*MATB)                // A, B0, B1 = 30720/stage
__global__ void __launch_bounds__(512, 1) k_mma1(){
    constexpr int K = Mdim;
    constexpr int NKS = K / 32;

    extern __shared__ __align__(128) char smem[];
    const uint32_t sb = s2u(smem);

    const int tid  = threadIdx.x;
    const int lane = tid & 31;
    const int wrp  = tid >> 5;
    const int wm   = (wrp >> 2) * 32;
    const int wn   = (wrp & 3) * 32;
    const int e  = blockIdx.z;
    const int bm = blockIdx.y * 128;
    const int bn = blockIdx.x * 128;

    const char* pA  = (const char*)(g_a   + ((size_t)e*GCv + bm)*K);
    const char* pB0 = (const char*)(g_w0t + ((size_t)e*Hp  + bn)*K);
    const char* pB1 = (const char*)(g_w1t + ((size_t)e*Hp  + bn)*K);

    const int rc = tid >> 2, qc = (tid & 3)*16;

    auto load_stage = [&](int ks, int buf){
        uint32_t s = sb + buf*STG1;
        size_t go = (size_t)rc*(K*2) + (size_t)ks*64 + qc;
        uint32_t so = (uint32_t)(rc*ROWB + qc);
        cpa16(s +          so, pA  + go);
        cpa16(s + MATB   + so, pB0 + go);
        cpa16(s + 2*MATB + so, pB1 + go);
        CP_COMMIT();
    };

    float d0[2][4][4], d1[2][4][4];
#pragma unroll
    for (int i = 0; i < 2; i++)
#pragma unroll
        for (int j = 0; j < 4; j++)
#pragma unroll
            for (int q = 0; q < 4; q++){ d0[i][j][q] = 0.f; d1[i][j][q] = 0.f; }

    load_stage(0, 0);
    load_stage(1, 1);

    for (int ks = 0; ks < NKS; ks++){
        if (ks < NKS-1) CP_WAIT1(); else CP_WAIT0();
        __syncthreads();
        if (ks + 2 < NKS) load_stage(ks + 2, (ks + 2) % 3);

        uint32_t s0 = sb + (ks % 3)*STG1;
#pragma unroll
        for (int kk = 0; kk < 2; kk++){
            uint32_t a[2][4], b0[4][2], b1[4][2];
#pragma unroll
            for (int mt = 0; mt < 2; mt++){
                uint32_t ad = s0 + (uint32_t)(wm + mt*16 + (lane & 15))*ROWB
                                 + (uint32_t)(kk*16 + (lane >> 4)*8)*2;
                LDSM4(a[mt], ad);
            }
#pragma unroll
            for (int nt = 0; nt < 4; nt++){
                uint32_t bd = s0 + (uint32_t)(wn + nt*8 + (lane & 7))*ROWB
                                 + (uint32_t)(kk*16 + ((lane >> 3) & 1)*8)*2;
                LDSM2(b0[nt], bd + MATB);
                LDSM2(b1[nt], bd + 2*MATB);
            }
#pragma unroll
            for (int mt = 0; mt < 2; mt++)
#pragma unroll
                for (int nt = 0; nt < 4; nt++){
                    MMA_F16(d0[mt][nt], a[mt], b0[nt]);
                    MMA_F16(d1[mt][nt], a[mt], b1[nt]);
                }
        }
    }

    const int rb = bm + wm + (lane >> 2);
    const int cb = bn + wn + 2*(lane & 3);
#pragma unroll
    for (int mt = 0; mt < 2; mt++)
#pragma unroll
        for (int nt = 0; nt < 4; nt++)
#pragma unroll
            for (int h = 0; h < 2; h++){
                int row = rb + mt*16 + h*8;
                int col = cb + nt*8;
                float ha = gelu_f(d0[mt][nt][h*2+0]) * d1[mt][nt][h*2+0];
                float hb = gelu_f(d0[mt][nt][h*2+1]) * d1[mt][nt][h*2+1];
                size_t idx = ((size_t)e*GCv + row)*(size_t)Hp + col;
                *(uint32_t*)(g_hid + idx) = packh(ha, hb);
            }
}

// ---------- GEMM2 (fp16): hid x woT -> expout fp32 ----------
#define STG2 (2*MATB)                // A, B = 20480/stage
__global__ void __launch_bounds__(512, 1) k_mma2(){
    constexpr int K = Hp;
    constexpr int N = Mdim;
    constexpr int NKS = K / 32;

    extern __shared__ __align__(128) char smem[];
    const uint32_t sb = s2u(smem);

    const int tid  = threadIdx.x;
    const int lane = tid & 31;
    const int wrp  = tid >> 5;
    const int wm   = (wrp >> 2) * 32;
    const int wn   = (wrp & 3) * 32;
    const int e  = blockIdx.z;
    const int bm = blockIdx.y * 128;
    const int bn = blockIdx.x * 128;

    const char* pA = (const char*)(g_hid + ((size_t)e*GCv + bm)*K);
    const char* pB = (const char*)(g_wot + ((size_t)e*N   + bn)*K);

    const int rc = tid >> 2, qc = (tid & 3)*16;

    auto load_stage = [&](int ks, int buf){
        uint32_t s = sb + buf*STG2;
        size_t go = (size_t)rc*(K*2) + (size_t)ks*64 + qc;
        uint32_t so = (uint32_t)(rc*ROWB + qc);
        cpa16(s +        so, pA + go);
        cpa16(s + MATB + so, pB + go);
        CP_COMMIT();
    };

    float d[2][4][4];
#pragma unroll
    for (int i = 0; i < 2; i++)
#pragma unroll
        for (int j = 0; j < 4; j++)
#pragma unroll
            for (int q = 0; q < 4; q++) d[i][j][q] = 0.f;

    load_stage(0, 0);
    load_stage(1, 1);

    for (int ks = 0; ks < NKS; ks++){
        if (ks < NKS-1) CP_WAIT1(); else CP_WAIT0();
        __syncthreads();
        if (ks + 2 < NKS) load_stage(ks + 2, (ks + 2) % 3);

        uint32_t s0 = sb + (ks % 3)*STG2;
#pragma unroll
        for (int kk = 0; kk < 2; kk++){
            uint32_t a[2][4], b[4][2];
#pragma unroll
            for (int mt = 0; mt < 2; mt++){
                uint32_t ad = s0 + (uint32_t)(wm + mt*16 + (lane & 15))*ROWB
                                 + (uint32_t)(kk*16 + (lane >> 4)*8)*2;
                LDSM4(a[mt], ad);
            }
#pragma unroll
            for (int nt = 0; nt < 4; nt++){
                uint32_t bd = s0 + MATB + (uint32_t)(wn + nt*8 + (lane & 7))*ROWB
                                 + (uint32_t)(kk*16 + ((lane >> 3) & 1)*8)*2;
                LDSM2(b[nt], bd);
            }
#pragma unroll
            for (int mt = 0; mt < 2; mt++)
#pragma unroll
                for (int nt = 0; nt < 4; nt++)
                    MMA_F16(d[mt][nt], a[mt], b[nt]);
        }
    }

    const int rb = bm + wm + (lane >> 2);
    const int cb = bn + wn + 2*(lane & 3);
#pragma unroll
    for (int mt = 0; mt < 2; mt++)
#pragma unroll
        for (int nt = 0; nt < 4; nt++)
#pragma unroll
            for (int h = 0; h < 2; h++){
                int row = rb + mt*16 + h*8;
                int col = cb + nt*8;
                size_t idx = ((size_t)e*GCv + row)*(size_t)Mdim + col;
                *(float2*)(g_expout + idx) = make_float2(d[mt][nt][h*2+0], d[mt][nt][h*2+1]);
            }
}

// ---------- combine ----------
__global__ void k_combine(float* __restrict__ out){
    int t = blockIdx.x, i = threadIdx.x;
    int2 info = g_tokinfo[t];
    float4 acc = make_float4(0.f,0.f,0.f,0.f);
    if (info.x >= 0){
        float gv = g_gate1[t];
        float4 v = ((const float4*)(g_expout + (size_t)info.x*Mdim))[i];
        acc.x += gv*v.x; acc.y += gv*v.y; acc.z += gv*v.z; acc.w += gv*v.w;
    }
    if (info.y >= 0){
        float gv = g_gate2[t];
        float4 v = ((const float4*)(g_expout + (size_t)info.y*Mdim))[i];
        acc.x += gv*v.x; acc.y += gv*v.y; acc.z += gv*v.z; acc.w += gv*v.w;
    }
    ((float4*)(out + (size_t)t*Mdim))[i] = acc;
}

// ---------- launch ----------
extern "C" void kernel_launch(void* const* d_in, const int* in_sizes, int n_in,
                              void* d_out, int out_size){
    const float* x  = (const float*)d_in[0];
    const float* rw = (const float*)d_in[1];
    const float* w0 = (const float*)d_in[2];
    const float* w1 = (const float*)d_in[3];
    const float* wo = (const float*)d_in[4];
    float* out = (float*)d_out;

    static bool attr_done = false;
    if (!attr_done){
        cudaFuncSetAttribute(k_mma1, cudaFuncAttributeMaxDynamicSharedMemorySize, 3*STG1);
        cudaFuncSetAttribute(k_mma2, cudaFuncAttributeMaxDynamicSharedMemorySize, 3*STG2);
        attr_done = true;
    }

    // k_mma1 is the 4th launch (the one ncu captures)
    k_router<<<Ntok/8, 256>>>(x, rw);                                    // 1
    k_capacity<<<Gg, 256>>>();                                           // 2
    k_prep<<<NGATH + 2*NSPL + NSPLW, 256>>>(x, w0, w1, wo);              // 3
    k_mma1<<<dim3(Hp/128,  GCv/128, Ee), 512, 3*STG1>>>();               // 4 <- profiled
    k_mma2<<<dim3(Mdim/128, GCv/128, Ee), 512, 3*STG2>>>();              // 5
    k_combine<<<Ntok, 256>>>(out);                                       // 6
}